// round 9
// baseline (speedup 1.0000x reference)
#include <cuda_runtime.h>
#include <cstdint>

// out[b, g, k, c] = textures[b, group_idx[g, k], c]
// B=2, T=1e6, C=16 (fp32), G=500000, K=9.
//
// R9: final occupancy push. R8 hit DRAM=81% at occ 64% (6 CTAs/SM, 40 regs).
// U=2 + __launch_bounds__(256,8) targets <=32 regs -> 8 CTAs/SM, 100%
// theoretical occupancy. Per-thread in-flight drops 96B->64B but warps/SM
// rise 48->64, keeping chip-level MLP flat while adding independent warps to
// cover store phases and wave tails. Loads: LDG.256 L2::evict_last.
// Stores: STG.256 evict-first. Same 32B-chunk decomposition as R7/R8.

#define U 2

__device__ __forceinline__ void ldg256_evict_last(const float4* p, unsigned long long d[4]) {
    asm volatile("ld.global.nc.L2::evict_last.v4.b64 {%0,%1,%2,%3}, [%4];"
                 : "=l"(d[0]), "=l"(d[1]), "=l"(d[2]), "=l"(d[3])
                 : "l"(p));
}

__device__ __forceinline__ void stg256_cs(float4* p, const unsigned long long d[4]) {
    asm volatile("st.global.cs.v4.b64 [%0], {%1,%2,%3,%4};"
                 :: "l"(p), "l"(d[0]), "l"(d[1]), "l"(d[2]), "l"(d[3]) : "memory");
}

__global__ void __launch_bounds__(256, 8)
tmscnn_gather_kernel(const float4* __restrict__ tex,     // [B, T*C/4]
                     const int*    __restrict__ gidx,    // [G*K]
                     float4*       __restrict__ out,     // [B, G*K*4]
                     int total32,                        // G*K*2 (32B chunks)
                     long long tex_batch_stride_f4,      // T*C/4
                     long long out_batch_stride_f4)      // G*K*4
{
    const int stride = gridDim.x * blockDim.x;
    const int i0 = blockIdx.x * blockDim.x + threadIdx.x;
    const int b = blockIdx.y;

    const float4* tex_b = tex + (long long)b * tex_batch_stride_f4;
    float4*       out_b = out + (long long)b * out_batch_stride_f4;

    int ii[U];
    int tt[U];
    unsigned long long vv[U][4];

    // Phase 1: independent index loads (2 lanes share one idx)
    #pragma unroll
    for (int u = 0; u < U; u++) {
        ii[u] = i0 + u * stride;
        tt[u] = 0;
        if (ii[u] < total32)
            tt[u] = __ldg(gidx + (ii[u] >> 1));
    }

    // Phase 2: independent 32B gathers, LDG.256 with L2 evict_last
    #pragma unroll
    for (int u = 0; u < U; u++) {
        if (ii[u] < total32) {
            const float4* src = tex_b + (long long)tt[u] * 4 + (ii[u] & 1) * 2;
            ldg256_evict_last(src, vv[u]);
        }
    }

    // Phase 3: evict-first streaming stores, one STG.256 per chunk
    #pragma unroll
    for (int u = 0; u < U; u++) {
        if (ii[u] < total32)
            stg256_cs(out_b + (long long)ii[u] * 2, vv[u]);
    }
}

extern "C" void kernel_launch(void* const* d_in, const int* in_sizes, int n_in,
                              void* d_out, int out_size)
{
    // metadata order: mesh_ids [B] int32, textures [B,T,C] f32, group_idx [G,K] int32
    const float* textures = (const float*)d_in[1];
    const int*   gidx     = (const int*)d_in[2];
    float*       out      = (float*)d_out;

    int B  = in_sizes[0];             // 2
    int GK = in_sizes[2];             // G*K = 4,500,000
    long long TC = (long long)in_sizes[1] / B;   // T*C = 16,000,000

    int total32 = GK * 2;             // 9,000,000 32B chunks per batch
    long long tex_stride_f4 = TC / 4; // 4,000,000
    long long out_stride_f4 = (long long)GK * 4;

    int threads_needed = (total32 + U - 1) / U;
    dim3 block(256);
    dim3 grid((threads_needed + 255) / 256, B);

    tmscnn_gather_kernel<<<grid, block>>>(
        (const float4*)textures, gidx, (float4*)out,
        total32, tex_stride_f4, out_stride_f4);
}

// round 10
// speedup vs baseline: 1.0015x; 1.0015x over previous
#include <cuda_runtime.h>
#include <cstdint>

// out[b, g, k, c] = textures[b, group_idx[g, k], c]
// B=2, T=1e6, C=16 (fp32), G=500000, K=9.
//
// R10: batch-sequential dispatch + evict_last (the untested combination).
// R7-R9 ran grid.y=2 => both 64MB textures live => 128MB of evict_last lines
// overflow the 126MB L2 and evict each other (hit rate stuck at 43%,
// traffic 940MB). A 1D grid with batch 0 in bids [0,bpb) serializes the
// batches (~15 waves each), so only one 64MB texture is live and can be
// pinned by evict_last. Unlike R4, the batch decode is kept to ~2 regs so
// 8 CTAs/SM is preserved (R4 regressed via 56 regs, not via the dispatch).

#define U 2

__device__ __forceinline__ void ldg256_evict_last(const float4* p, unsigned long long d[4]) {
    asm volatile("ld.global.nc.L2::evict_last.v4.b64 {%0,%1,%2,%3}, [%4];"
                 : "=l"(d[0]), "=l"(d[1]), "=l"(d[2]), "=l"(d[3])
                 : "l"(p));
}

__device__ __forceinline__ void stg256_cs(float4* p, const unsigned long long d[4]) {
    asm volatile("st.global.cs.v4.b64 [%0], {%1,%2,%3,%4};"
                 :: "l"(p), "l"(d[0]), "l"(d[1]), "l"(d[2]), "l"(d[3]) : "memory");
}

__global__ void __launch_bounds__(256, 8)
tmscnn_gather_kernel(const float4* __restrict__ tex,     // [B, T*C/4]
                     const int*    __restrict__ gidx,    // [G*K]
                     float4*       __restrict__ out,     // [B, G*K*4]
                     int total32,                        // G*K*2 (32B chunks)
                     int blocks_per_batch,
                     long long tex_batch_stride_f4,      // T*C/4
                     long long out_batch_stride_f4)      // G*K*4
{
    // Batch 0: bids [0, bpb) -> dispatched first; batch 1: the rest.
    int bid = blockIdx.x;
    bool b1 = (bid >= blocks_per_batch);
    if (b1) bid -= blocks_per_batch;

    const int stride = blocks_per_batch * blockDim.x;
    const int i0 = bid * blockDim.x + threadIdx.x;

    const float4* tex_b = tex + (b1 ? tex_batch_stride_f4 : 0);
    float4*       out_b = out + (b1 ? out_batch_stride_f4 : 0);

    int ii[U];
    int tt[U];
    unsigned long long vv[U][4];

    // Phase 1: independent index loads (2 lanes share one idx)
    #pragma unroll
    for (int u = 0; u < U; u++) {
        ii[u] = i0 + u * stride;
        tt[u] = 0;
        if (ii[u] < total32)
            tt[u] = __ldg(gidx + (ii[u] >> 1));
    }

    // Phase 2: independent 32B gathers, LDG.256 with L2 evict_last
    #pragma unroll
    for (int u = 0; u < U; u++) {
        if (ii[u] < total32) {
            const float4* src = tex_b + (long long)tt[u] * 4 + (ii[u] & 1) * 2;
            ldg256_evict_last(src, vv[u]);
        }
    }

    // Phase 3: evict-first streaming stores, one STG.256 per chunk
    #pragma unroll
    for (int u = 0; u < U; u++) {
        if (ii[u] < total32)
            stg256_cs(out_b + (long long)ii[u] * 2, vv[u]);
    }
}

extern "C" void kernel_launch(void* const* d_in, const int* in_sizes, int n_in,
                              void* d_out, int out_size)
{
    // metadata order: mesh_ids [B] int32, textures [B,T,C] f32, group_idx [G,K] int32
    const float* textures = (const float*)d_in[1];
    const int*   gidx     = (const int*)d_in[2];
    float*       out      = (float*)d_out;

    int B  = in_sizes[0];             // 2
    int GK = in_sizes[2];             // G*K = 4,500,000
    long long TC = (long long)in_sizes[1] / B;   // T*C = 16,000,000

    int total32 = GK * 2;             // 9,000,000 32B chunks per batch
    long long tex_stride_f4 = TC / 4; // 4,000,000
    long long out_stride_f4 = (long long)GK * 4;

    int threads_needed = (total32 + U - 1) / U;
    int blocks_per_batch = (threads_needed + 255) / 256;

    dim3 block(256);
    dim3 grid(blocks_per_batch * B);

    tmscnn_gather_kernel<<<grid, block>>>(
        (const float4*)textures, gidx, (float4*)out,
        total32, blocks_per_batch, tex_stride_f4, out_stride_f4);
}